// round 1
// baseline (speedup 1.0000x reference)
#include <cuda_runtime.h>

#define BB 64
#define CC 512
#define TT 16
#define HWD 196
#define KK 8

// [b][t][c] per-channel partial scores (written fully each launch)
__device__ float g_partial[BB * TT * CC];
__device__ float g_score[BB * TT];
__device__ int   g_idx[2 * BB * KK];   // [half][b][j], half 0=approx 1=detail

// ---------------------------------------------------------------------------
// Kernel 1: one block per (b,c). Stage the contiguous 16x196 slab to smem,
// 2x2 avg-pool to 16x49, compute column sums Sc[blk] = sum_t pooled[t][blk],
// then partial[t] = sum_blk pooled[t][blk] * Sc[blk]  (== <xi_t, S> for this c)
// ---------------------------------------------------------------------------
__global__ void k_pool(const float* __restrict__ x) {
    __shared__ float raw[TT * HWD];       // 3136 floats
    __shared__ float pooled[TT * 49];     // 784 floats
    __shared__ float sc[49];

    const int bc = blockIdx.x;            // b*CC + c
    const float4* __restrict__ src = (const float4*)(x + (size_t)bc * (TT * HWD));
    float4* rawv = (float4*)raw;
    for (int i = threadIdx.x; i < (TT * HWD) / 4; i += blockDim.x)
        rawv[i] = src[i];
    __syncthreads();

    for (int p = threadIdx.x; p < TT * 49; p += blockDim.x) {
        int t = p / 49, blk = p - t * 49;
        int by = blk / 7, bx = blk - by * 7;
        const float* r = raw + t * HWD + by * 28 + bx * 2;
        pooled[p] = 0.25f * (r[0] + r[1] + r[14] + r[15]);
    }
    __syncthreads();

    if (threadIdx.x < 49) {
        float s = 0.f;
        #pragma unroll
        for (int t = 0; t < TT; t++) s += pooled[t * 49 + threadIdx.x];
        sc[threadIdx.x] = s;
    }
    __syncthreads();

    if (threadIdx.x < TT) {
        float acc = 0.f;
        #pragma unroll
        for (int blk = 0; blk < 49; blk++)
            acc += pooled[threadIdx.x * 49 + blk] * sc[blk];
        int b = bc >> 9, c = bc & (CC - 1);
        g_partial[(b * TT + threadIdx.x) * CC + c] = acc;
    }
}

// ---------------------------------------------------------------------------
// Kernel 2: deterministic fixed-order reduction over channels. 1 block per (b,t)
// ---------------------------------------------------------------------------
__global__ void k_reduce() {
    __shared__ float sm[128];
    const int bt = blockIdx.x;
    const float* __restrict__ p = g_partial + bt * CC;
    float s = p[threadIdx.x] + p[threadIdx.x + 128] + p[threadIdx.x + 256] + p[threadIdx.x + 384];
    sm[threadIdx.x] = s;
    __syncthreads();
    #pragma unroll
    for (int off = 64; off > 0; off >>= 1) {
        if (threadIdx.x < off) sm[threadIdx.x] += sm[threadIdx.x + off];
        __syncthreads();
    }
    if (threadIdx.x == 0)
        g_score[bt] = sm[0] * (1.0f / (float)(CC * TT));   // scaler/T
}

// ---------------------------------------------------------------------------
// Kernel 3: per-batch selection. Replicates jax.lax.top_k tie semantics
// (value order, ties by smaller index) independently for approx (largest)
// and detail (smallest), then emits indices in ascending-t order (== sorted).
// ---------------------------------------------------------------------------
__global__ void k_select() {
    __shared__ float v[TT];
    __shared__ int fa[TT], fd[TT];
    const int b = blockIdx.x, t = threadIdx.x;
    v[t] = g_score[b * TT + t] + ((t & 1) == 0 ? 1.0f : 0.0f);
    __syncthreads();
    const float mv = v[t];
    int ra = 0, rd = 0;
    #pragma unroll
    for (int s = 0; s < TT; s++) {
        ra += (v[s] > mv) || (v[s] == mv && s < t);
        rd += (v[s] < mv) || (v[s] == mv && s < t);
    }
    fa[t] = (ra < KK);
    fd[t] = (rd < KK);
    __syncthreads();
    int pa = 0, pd = 0;
    for (int s = 0; s < t; s++) { pa += fa[s]; pd += fd[s]; }
    if (fa[t]) g_idx[b * KK + pa] = t;
    if (fd[t]) g_idx[BB * KK + b * KK + pd] = t;
}

// ---------------------------------------------------------------------------
// Kernel 4: gather. out = [x_a (b,c,8,196)] ++ [x_d (b,c,8,196)], float4 copy.
// ---------------------------------------------------------------------------
#define TOTAL4 (2 * BB * CC * KK * (HWD / 4))   // 25,690,112

__global__ void k_gather(const float* __restrict__ x, float* __restrict__ out) {
    int i = blockIdx.x * blockDim.x + threadIdx.x;
    if (i >= TOTAL4) return;
    int hw4 = i % 49;
    int r = i / 49;
    int j = r & (KK - 1);      r >>= 3;
    int c = r & (CC - 1);      r >>= 9;
    int b = r & (BB - 1);
    int half = r >> 6;
    int t = __ldg(&g_idx[half * (BB * KK) + b * KK + j]);
    const float4* __restrict__ src = (const float4*)x;
    float4 val = __ldg(&src[((b * CC + c) * TT + t) * 49 + hw4]);
    ((float4*)out)[i] = val;
}

// ---------------------------------------------------------------------------
extern "C" void kernel_launch(void* const* d_in, const int* in_sizes, int n_in,
                              void* d_out, int out_size) {
    const float* x = (const float*)d_in[0];
    float* out = (float*)d_out;

    k_pool<<<BB * CC, 256>>>(x);
    k_reduce<<<BB * TT, 128>>>();
    k_select<<<BB, TT>>>();
    k_gather<<<(TOTAL4 + 255) / 256, 256>>>(x, out);
}

// round 2
// speedup vs baseline: 1.1672x; 1.1672x over previous
#include <cuda_runtime.h>

#define BB 64
#define CC 512
#define TT 16
#define HWD 196
#define KK 8

// [b][t][c] per-channel partial scores
__device__ float g_partial[BB * TT * CC];
// [b][t] -> output slot 0..15 (0-7 = approx pos, 8-15 = 8+detail pos)
__device__ int   g_dest[BB * TT];

// ---------------------------------------------------------------------------
// Kernel 1: one block per (b,c), 256 threads.
//   stage L: stage contiguous 16x196 slab to smem (float4)
//   stage C: csum[hw]  = sum_t raw[t][hw]            (196 threads, 16 LDS each)
//   stage S: sc[blk]   = 0.25 * 2x2-pool of csum     (49 threads)
//   stage D: thread (t=tid>>4, g=tid&15) accumulates
//            sum over blk in {g, g+16, ...} of pooled[t][blk]*sc[blk],
//            half-warp shuffle reduce over g -> partial[b][t][c]
// ---------------------------------------------------------------------------
__global__ __launch_bounds__(256) void k_pool(const float* __restrict__ x) {
    __shared__ float raw[TT * HWD];   // 3136
    __shared__ float csum[HWD];       // 196
    __shared__ float sc[49];

    const int bc = blockIdx.x;        // b*CC + c
    const float4* __restrict__ src = (const float4*)(x + (size_t)bc * (TT * HWD));
    float4* rawv = (float4*)raw;
    #pragma unroll
    for (int i = threadIdx.x; i < (TT * HWD) / 4; i += 256)
        rawv[i] = src[i];
    __syncthreads();

    if (threadIdx.x < HWD) {
        float s = 0.f;
        #pragma unroll
        for (int t = 0; t < TT; t++) s += raw[t * HWD + threadIdx.x];
        csum[threadIdx.x] = s;
    }
    __syncthreads();

    if (threadIdx.x < 49) {
        int by = threadIdx.x / 7, bx = threadIdx.x - by * 7;
        const float* r = csum + by * 28 + bx * 2;
        sc[threadIdx.x] = 0.25f * (r[0] + r[1] + r[14] + r[15]);
    }
    __syncthreads();

    const int t = threadIdx.x >> 4;
    const int g = threadIdx.x & 15;
    float acc = 0.f;
    #pragma unroll
    for (int blk = g; blk < 49; blk += 16) {
        int by = blk / 7, bx = blk - by * 7;
        const float* r = raw + t * HWD + by * 28 + bx * 2;
        float pooled = 0.25f * (r[0] + r[1] + r[14] + r[15]);
        acc += pooled * sc[blk];
    }
    // reduce over the 16-lane g-group (stays inside a warp: xor <= 15)
    acc += __shfl_xor_sync(0xffffffffu, acc, 8);
    acc += __shfl_xor_sync(0xffffffffu, acc, 4);
    acc += __shfl_xor_sync(0xffffffffu, acc, 2);
    acc += __shfl_xor_sync(0xffffffffu, acc, 1);
    if (g == 0) {
        int b = bc >> 9, c = bc & (CC - 1);
        g_partial[(b * TT + t) * CC + c] = acc;
    }
}

// ---------------------------------------------------------------------------
// Kernel 2: fused channel-reduce + selection. One block per b, 256 threads.
// Thread (t=tid>>4, g=tid&15) sums 32 channels (coalesced), half-warp shuffle
// reduce -> score[t]; then jax.lax.top_k tie semantics (value desc/asc, ties
// by smaller index) to produce per-frame destination slots.
// ---------------------------------------------------------------------------
__global__ __launch_bounds__(256) void k_score_select() {
    __shared__ float v[TT];
    __shared__ int fa[TT], fd[TT];
    const int b = blockIdx.x;
    const int t = threadIdx.x >> 4;
    const int g = threadIdx.x & 15;

    const float* __restrict__ p = g_partial + (b * TT + t) * CC;
    float s = 0.f;
    #pragma unroll
    for (int j = 0; j < CC / 16; j++) s += p[g + 16 * j];
    s += __shfl_xor_sync(0xffffffffu, s, 8);
    s += __shfl_xor_sync(0xffffffffu, s, 4);
    s += __shfl_xor_sync(0xffffffffu, s, 2);
    s += __shfl_xor_sync(0xffffffffu, s, 1);
    if (g == 0)
        v[t] = s * (1.0f / (float)(CC * TT)) + ((t & 1) == 0 ? 1.0f : 0.0f);
    __syncthreads();

    if (threadIdx.x < TT) {
        const int i = threadIdx.x;
        const float mv = v[i];
        int ra = 0, rd = 0;
        #pragma unroll
        for (int j = 0; j < TT; j++) {
            ra += (v[j] > mv) || (v[j] == mv && j < i);
            rd += (v[j] < mv) || (v[j] == mv && j < i);
        }
        fa[i] = (ra < KK);
        fd[i] = (rd < KK);
    }
    __syncthreads();
    if (threadIdx.x < TT) {
        const int i = threadIdx.x;
        int pa = 0, pd = 0;
        for (int j = 0; j < i; j++) { pa += fa[j]; pd += fd[j]; }
        // ranks form a permutation (ra+rd==15): exactly one of fa/fd is set
        g_dest[b * TT + i] = fa[i] ? pa : (KK + pd);
    }
}

// ---------------------------------------------------------------------------
// Kernel 3: gather. Sequential coalesced READ of the whole input; permuted
// frame-granular WRITE into [x_a ; x_d].
// ---------------------------------------------------------------------------
#define TOTAL4 (BB * CC * TT * (HWD / 4))   // 25,690,112 float4s

__global__ __launch_bounds__(256) void k_gather(const float* __restrict__ x,
                                                float* __restrict__ out) {
    unsigned i = blockIdx.x * 256 + threadIdx.x;
    if (i >= TOTAL4) return;
    float4 val = __ldg(&((const float4*)x)[i]);
    unsigned hw4 = i % 49u;
    unsigned r = i / 49u;
    unsigned t = r & (TT - 1);
    unsigned c = (r >> 4) & (CC - 1);
    unsigned b = r >> 13;
    int s = __ldg(&g_dest[b * TT + t]);
    unsigned half = (unsigned)s >> 3;
    unsigned j = (unsigned)s & (KK - 1);
    unsigned o = half * (BB * CC * KK * 49u) + ((b * CC + c) * KK + j) * 49u + hw4;
    ((float4*)out)[o] = val;
}

// ---------------------------------------------------------------------------
extern "C" void kernel_launch(void* const* d_in, const int* in_sizes, int n_in,
                              void* d_out, int out_size) {
    const float* x = (const float*)d_in[0];
    float* out = (float*)d_out;

    k_pool<<<BB * CC, 256>>>(x);
    k_score_select<<<BB, 256>>>();
    k_gather<<<(TOTAL4 + 255) / 256, 256>>>(x, out);
}

// round 3
// speedup vs baseline: 1.3075x; 1.1201x over previous
#include <cuda_runtime.h>

#define BB 64
#define CC 512
#define TT 16
#define HWD 196
#define KK 8

// [b][t][c] per-channel partial scores
__device__ float g_partial[BB * TT * CC];
// [b][t] -> output slot 0..15 (0-7 = approx pos, 8-15 = 8+detail pos)
__device__ int   g_dest[BB * TT];

// ---------------------------------------------------------------------------
// Kernel 1: one block per (b,c), 256 threads. No raw-slab staging:
//   phase 1: pooled[t][blk] computed directly from global via 2x LDG.64,
//            stored once to smem (784 floats)
//   phase 2: sc[blk] = sum_t pooled[t][blk]      (49 threads, conflict-free)
//   phase 3: thread (t=tid>>4, g=tid&15) accumulates pooled[t][blk]*sc[blk]
//            over blk in {g, g+16, g+32, g+48}, half-warp shuffle reduce.
// ---------------------------------------------------------------------------
__global__ __launch_bounds__(256) void k_pool(const float* __restrict__ x) {
    __shared__ float pooled[TT * 49];   // 784
    __shared__ float sc[49];

    const int bc = blockIdx.x;          // b*CC + c
    const float* __restrict__ slab = x + (size_t)bc * (TT * HWD);

    #pragma unroll
    for (int p = threadIdx.x; p < TT * 49; p += 256) {
        int t = p / 49, blk = p - t * 49;
        int by = blk / 7, bx = blk - by * 7;
        const float* r = slab + t * HWD + by * 28 + bx * 2;
        float2 a = *(const float2*)r;
        float2 b = *(const float2*)(r + 14);
        pooled[p] = 0.25f * (a.x + a.y + b.x + b.y);
    }
    __syncthreads();

    if (threadIdx.x < 49) {
        float s = 0.f;
        #pragma unroll
        for (int t = 0; t < TT; t++) s += pooled[t * 49 + threadIdx.x];
        sc[threadIdx.x] = s;
    }
    __syncthreads();

    const int t = threadIdx.x >> 4;
    const int g = threadIdx.x & 15;
    float acc = 0.f;
    #pragma unroll
    for (int blk = g; blk < 49; blk += 16)
        acc += pooled[t * 49 + blk] * sc[blk];
    acc += __shfl_xor_sync(0xffffffffu, acc, 8);
    acc += __shfl_xor_sync(0xffffffffu, acc, 4);
    acc += __shfl_xor_sync(0xffffffffu, acc, 2);
    acc += __shfl_xor_sync(0xffffffffu, acc, 1);
    if (g == 0) {
        int b = bc >> 9, c = bc & (CC - 1);
        g_partial[(b * TT + t) * CC + c] = acc;
    }
}

// ---------------------------------------------------------------------------
// Kernel 2: fused channel-reduce + selection. One block per b, 256 threads.
// Deterministic fixed-order sums; jax.lax.top_k tie semantics (ties by
// smaller index) for both largest (approx) and smallest (detail) halves.
// ---------------------------------------------------------------------------
__global__ __launch_bounds__(256) void k_score_select() {
    __shared__ float v[TT];
    __shared__ int fa[TT], fd[TT];
    const int b = blockIdx.x;
    const int t = threadIdx.x >> 4;
    const int g = threadIdx.x & 15;

    const float* __restrict__ p = g_partial + (b * TT + t) * CC;
    float s = 0.f;
    #pragma unroll
    for (int j = 0; j < CC / 16; j++) s += p[g + 16 * j];
    s += __shfl_xor_sync(0xffffffffu, s, 8);
    s += __shfl_xor_sync(0xffffffffu, s, 4);
    s += __shfl_xor_sync(0xffffffffu, s, 2);
    s += __shfl_xor_sync(0xffffffffu, s, 1);
    if (g == 0)
        v[t] = s * (1.0f / (float)(CC * TT)) + ((t & 1) == 0 ? 1.0f : 0.0f);
    __syncthreads();

    if (threadIdx.x < TT) {
        const int i = threadIdx.x;
        const float mv = v[i];
        int ra = 0, rd = 0;
        #pragma unroll
        for (int j = 0; j < TT; j++) {
            ra += (v[j] > mv) || (v[j] == mv && j < i);
            rd += (v[j] < mv) || (v[j] == mv && j < i);
        }
        fa[i] = (ra < KK);
        fd[i] = (rd < KK);
    }
    __syncthreads();
    if (threadIdx.x < TT) {
        const int i = threadIdx.x;
        int pa = 0, pd = 0;
        for (int j = 0; j < i; j++) { pa += fa[j]; pd += fd[j]; }
        // ranks form a permutation (ra+rd==15): exactly one of fa/fd is set
        g_dest[b * TT + i] = fa[i] ? pa : (KK + pd);
    }
}

// ---------------------------------------------------------------------------
// Kernel 3: gather. Sequential coalesced READ of the whole input; permuted
// frame-granular WRITE into [x_a ; x_d].
// ---------------------------------------------------------------------------
#define TOTAL4 (BB * CC * TT * (HWD / 4))   // 25,690,112 float4s

__global__ __launch_bounds__(256) void k_gather(const float* __restrict__ x,
                                                float* __restrict__ out) {
    unsigned i = blockIdx.x * 256 + threadIdx.x;
    if (i >= TOTAL4) return;
    float4 val = __ldg(&((const float4*)x)[i]);
    unsigned hw4 = i % 49u;
    unsigned r = i / 49u;
    unsigned t = r & (TT - 1);
    unsigned c = (r >> 4) & (CC - 1);
    unsigned b = r >> 13;
    int s = __ldg(&g_dest[b * TT + t]);
    unsigned half = (unsigned)s >> 3;
    unsigned j = (unsigned)s & (KK - 1);
    unsigned o = half * (BB * CC * KK * 49u) + ((b * CC + c) * KK + j) * 49u + hw4;
    ((float4*)out)[o] = val;
}

// ---------------------------------------------------------------------------
extern "C" void kernel_launch(void* const* d_in, const int* in_sizes, int n_in,
                              void* d_out, int out_size) {
    const float* x = (const float*)d_in[0];
    float* out = (float*)d_out;

    k_pool<<<BB * CC, 256>>>(x);
    k_score_select<<<BB, 256>>>();
    k_gather<<<(TOTAL4 + 255) / 256, 256>>>(x, out);
}